// round 8
// baseline (speedup 1.0000x reference)
#include <cuda_runtime.h>

#define Bc      128
#define Sc      37
#define Tc      2048
#define Dc      256
#define STc     8
#define Cc      2
#define Fc      (2 * Sc)        // 74
#define MERGEDc (Dc + STc)      // 264
#define SPLIT   4
#define CHUNK   (Tc / SPLIT)    // 512 t per CTA
#define NT1     128
#define W1      (NT1 / 32)      // 4 warps

// Per-batch partial sums, one row per CTA:
// [0..36]=sum x, [37..73]=sum mask, [74]=sum valid*time, [75]=sum valid
__device__ float        g_part[Bc][SPLIT][80];
__device__ unsigned int g_cnt[Bc];   // zero-init; last arriver resets to 0

__global__ __launch_bounds__(NT1, 4)
void fused_all(const float* __restrict__ x,        // [B,S,T]
               const int*   __restrict__ smask,    // [B,S,T]
               const float* __restrict__ time_in,  // [B,T]
               const float* __restrict__ stat_in,  // [B,ST]
               const float* __restrict__ W_sensor, // [2S,D]
               const float* __restrict__ b_sensor, // [D]
               const float* __restrict__ W_time,   // [1,D]
               const float* __restrict__ b_time,   // [D]
               const float* __restrict__ W_static, // [ST,ST]
               const float* __restrict__ b_static, // [ST]
               const float* __restrict__ W_merge,  // [MERGED,MERGED]
               const float* __restrict__ b_merge,  // [MERGED]
               const float* __restrict__ W_cls,    // [MERGED,C]
               const float* __restrict__ b_cls,    // [C]
               float* __restrict__ out)            // [B,C]
{
    const int blk  = blockIdx.x;
    const int b    = blk >> 2;
    const int part = blk & (SPLIT - 1);
    const int tid  = threadIdx.x;
    const int lane = tid & 31;
    const int warp = tid >> 5;
    const int t0   = part * CHUNK + tid * 4;

    // Vector-accessed shared buffers declared as float4 => 16B-aligned by type.
    __shared__ float4 sens_s4[2][Dc / 4];        // sensor partials (2 x 256 floats)
    __shared__ float4 merge_s4[2][MERGEDc / 4];  // merge partials  (2 x 264 floats)
    __shared__ float  st[W1][80];
    __shared__ float  sx[76];
    __shared__ float  comb[MERGEDc];
    __shared__ float  combr[MERGEDc];
    __shared__ int    is_last;

    // =====================================================================
    // Streaming phase (DRAM-bound, near roofline)
    // =====================================================================
    {
        const float4* xb = (const float4*)(x     + (size_t)b * Sc * Tc);
        const int4*   mb = (const int4*)  (smask + (size_t)b * Sc * Tc);

        float psum[Sc];
        int   pm[Sc];
        int v0 = 0, v1 = 0, v2 = 0, v3 = 0;

#pragma unroll
        for (int s = 0; s < Sc; ++s) {
            const int idx = (s * Tc + t0) >> 2;
            float4 xv = __ldg(&xb[idx]);
            int4   mv = __ldg(&mb[idx]);
            // valid[t]==0 => all features at t are 0 => plain sums == masked sums
            psum[s] = (xv.x + xv.y) + (xv.z + xv.w);
            pm[s]   = (mv.x + mv.y) + (mv.z + mv.w);
            v0 |= (int)((xv.x != 0.f) | (mv.x != 0));
            v1 |= (int)((xv.y != 0.f) | (mv.y != 0));
            v2 |= (int)((xv.z != 0.f) | (mv.z != 0));
            v3 |= (int)((xv.w != 0.f) | (mv.w != 0));
        }

        float4 tv = __ldg((const float4*)(time_in + (size_t)b * Tc) + (t0 >> 2));
        float tsum = (float)v0 * tv.x + (float)v1 * tv.y
                   + (float)v2 * tv.z + (float)v3 * tv.w;
        float den  = (float)(v0 + v1 + v2 + v3);

#pragma unroll
        for (int s = 0; s < Sc; ++s) {
#pragma unroll
            for (int o = 16; o > 0; o >>= 1) {
                psum[s] += __shfl_xor_sync(0xFFFFFFFFu, psum[s], o);
                pm[s]   += __shfl_xor_sync(0xFFFFFFFFu, pm[s],   o);
            }
        }
#pragma unroll
        for (int o = 16; o > 0; o >>= 1) {
            tsum += __shfl_xor_sync(0xFFFFFFFFu, tsum, o);
            den  += __shfl_xor_sync(0xFFFFFFFFu, den,  o);
        }

        if (lane == 0) {
#pragma unroll
            for (int s = 0; s < Sc; ++s) {
                st[warp][s]      = psum[s];
                st[warp][Sc + s] = (float)pm[s];
            }
            st[warp][Fc]     = tsum;
            st[warp][Fc + 1] = den;
        }
        __syncthreads();

        if (tid < 76) {
            g_part[b][part][tid] = (st[0][tid] + st[1][tid])
                                 + (st[2][tid] + st[3][tid]);
        }
    }

    // =====================================================================
    // Last-CTA-per-batch election
    // =====================================================================
    __threadfence();              // publish g_part writes
    __syncthreads();

    if (tid == 0) {
        unsigned int old = atomicAdd(&g_cnt[b], 1u);
        is_last = (old == SPLIT - 1);
        if (is_last) g_cnt[b] = 0;   // reset for next graph replay
    }
    __syncthreads();
    if (!is_last) return;
    __threadfence();              // acquire side

    // =====================================================================
    // MLP head for batch b (overlaps other batches' streaming)
    // =====================================================================
    if (tid < 76) {
        sx[tid] = (g_part[b][0][tid] + g_part[b][1][tid])
                + (g_part[b][2][tid] + g_part[b][3][tid]);
    }
    __syncthreads();

    const float denomR = sx[Fc + 1];
    const float denomC = fmaxf(denomR, 1e-9f);
    const float tsumR  = sx[Fc];

    // ---- sensor projection: 2 f-groups (37 each) x 64 d-quads, float4
    {
        const int g  = tid >> 6;      // 0..1
        const int q  = tid & 63;      // d-quad
        const int f0 = g * 37;
        float4 acc = make_float4(0.f, 0.f, 0.f, 0.f);
#pragma unroll
        for (int k = 0; k < 37; ++k) {
            const float  s = sx[f0 + k];
            const float4 w = __ldg((const float4*)(W_sensor + (f0 + k) * Dc) + q);
            acc.x += s * w.x; acc.y += s * w.y;
            acc.z += s * w.z; acc.w += s * w.w;
        }
        sens_s4[g][q] = acc;
    }
    __syncthreads();

    // ---- combine + time/bias; static embedding
    {
        const float* s0 = (const float*)sens_s4[0];
        const float* s1 = (const float*)sens_s4[1];
        for (int d = tid; d < Dc; d += NT1) {
            float a = s0[d] + s1[d]
                    + tsumR  * __ldg(&W_time[d])
                    + denomR * (__ldg(&b_sensor[d]) + __ldg(&b_time[d]));
            comb[d] = a / denomC;
        }
    }
    if (tid < STc) {
        const int j = tid;
        float a = __ldg(&b_static[j]);
#pragma unroll
        for (int i = 0; i < STc; ++i)
            a += __ldg(&stat_in[b * STc + i]) * __ldg(&W_static[i * STc + j]);
        comb[Dc + j] = a;
    }
    __syncthreads();

    // ---- merge: 2 i-groups (132 each) x 66 j-quads, float4
    {
        const int g  = tid >> 6;      // 0..1
        const int q  = tid & 63;      // quads 0..63
        const int i0 = g * 132;
        float4 acc = make_float4(0.f, 0.f, 0.f, 0.f);
#pragma unroll 8
        for (int k = 0; k < 132; ++k) {
            const float  c = comb[i0 + k];
            const float4 w = __ldg((const float4*)(W_merge + (i0 + k) * MERGEDc) + q);
            acc.x += c * w.x; acc.y += c * w.y;
            acc.z += c * w.z; acc.w += c * w.w;
        }
        merge_s4[g][q] = acc;

        // tail quads 64,65 for both i-groups: 4 tasks on tid<4
        if (tid < 4) {
            const int gg  = tid >> 1;
            const int qq  = 64 + (tid & 1);
            const int ii0 = gg * 132;
            float4 a2 = make_float4(0.f, 0.f, 0.f, 0.f);
#pragma unroll 8
            for (int k = 0; k < 132; ++k) {
                const float  c = comb[ii0 + k];
                const float4 w = __ldg((const float4*)(W_merge + (ii0 + k) * MERGEDc) + qq);
                a2.x += c * w.x; a2.y += c * w.y;
                a2.z += c * w.z; a2.w += c * w.w;
            }
            merge_s4[gg][qq] = a2;
        }
    }
    __syncthreads();

    {
        const float* m0 = (const float*)merge_s4[0];
        const float* m1 = (const float*)merge_s4[1];
        for (int j = tid; j < MERGEDc; j += NT1) {
            float a = __ldg(&b_merge[j]) + m0[j] + m1[j];
            combr[j] = fmaxf(a, 0.f);
        }
    }
    __syncthreads();

    // ---- classifier (warp 0)
    if (tid < 32) {
        float c0 = 0.f, c1 = 0.f;
        for (int i = lane; i < MERGEDc; i += 32) {
            const float v = combr[i];
            c0 += v * __ldg(&W_cls[i * Cc + 0]);
            c1 += v * __ldg(&W_cls[i * Cc + 1]);
        }
#pragma unroll
        for (int o = 16; o > 0; o >>= 1) {
            c0 += __shfl_xor_sync(0xFFFFFFFFu, c0, o);
            c1 += __shfl_xor_sync(0xFFFFFFFFu, c1, o);
        }
        if (lane == 0) {
            out[b * Cc + 0] = c0 + __ldg(&b_cls[0]);
            out[b * Cc + 1] = c1 + __ldg(&b_cls[1]);
        }
    }
}

extern "C" void kernel_launch(void* const* d_in, const int* in_sizes, int n_in,
                              void* d_out, int out_size)
{
    const float* x        = (const float*)d_in[0];
    const float* stat_in  = (const float*)d_in[1];
    const float* time_in  = (const float*)d_in[2];
    const int*   smask    = (const int*)  d_in[3];
    const float* W_sensor = (const float*)d_in[4];
    const float* b_sensor = (const float*)d_in[5];
    const float* W_time   = (const float*)d_in[6];
    const float* b_time   = (const float*)d_in[7];
    const float* W_static = (const float*)d_in[8];
    const float* b_static = (const float*)d_in[9];
    const float* W_merge  = (const float*)d_in[10];
    const float* b_merge  = (const float*)d_in[11];
    const float* W_cls    = (const float*)d_in[12];
    const float* b_cls    = (const float*)d_in[13];
    float* out = (float*)d_out;

    fused_all<<<Bc * SPLIT, NT1>>>(x, smask, time_in, stat_in,
                                   W_sensor, b_sensor, W_time, b_time,
                                   W_static, b_static, W_merge, b_merge,
                                   W_cls, b_cls, out);
}